// round 3
// baseline (speedup 1.0000x reference)
#include <cuda_runtime.h>
#include <math.h>

#define NN   10000
#define EE   160000
#define GG   128
#define HID  25
#define DOUT 32
#define BEPS 1e-5f
#define HP   32          // padded h row
#define NB   30          // node-range blocks in k_y
#define KB   5           // k's per block in k_y
#define NT   8           // nodes per tile in k_y

typedef unsigned long long u64;

// ---------------- f32x2 helpers (bit-exact packed fp32 FMA) ------------------
__device__ __forceinline__ u64 pk2(float a, float b) {
    u64 r; asm("mov.b64 %0, {%1, %2};" : "=l"(r) : "f"(a), "f"(b)); return r;
}
__device__ __forceinline__ u64 fma2(u64 a, u64 b, u64 c) {
    u64 d; asm("fma.rn.f32x2 %0, %1, %2, %3;" : "=l"(d) : "l"(a), "l"(b), "l"(c)); return d;
}
__device__ __forceinline__ void upk2(u64 u, float& a, float& b) {
    asm("mov.b64 {%0, %1}, %2;" : "=f"(a), "=f"(b) : "l"(u));
}

// ---------------- scratch ----------------------------------------------------
__device__ float  d_h0[(size_t)EE * HP];        // layer0 h pre-BN, sorted, [p][32]
__device__ float  d_h1[(size_t)EE * HP];        // layer1
__device__ double d_sum[4 * HID];               // [layer][sum|sumsq][k]
__device__ float  d_y[(size_t)NN * HID * DOUT];
__device__ float  d_xb[NN * DOUT];
__device__ float  d_agg[NN * DOUT];
__device__ float  d_x0[NN * DOUT];
__device__ float  d_deg[NN];
__device__ int    d_degs[NN];
__device__ int    d_start[NN + 1];
__device__ int    d_cursor[NN];
__device__ int    d_perm[EE];
__device__ int    d_dsts[EE];
__device__ float  d_gsum[GG * DOUT];
__device__ float  d_gcnt[GG];

// ---------------- init -------------------------------------------------------
__global__ void k_init() {
    int i = blockIdx.x * blockDim.x + threadIdx.x;
    if (i < NN)        { d_deg[i] = 0.f; d_degs[i] = 0; }
    if (i < 4 * HID)   d_sum[i] = 0.0;
    if (i < GG * DOUT) d_gsum[i] = 0.f;
    if (i < GG)        d_gcnt[i] = 0.f;
}

__global__ void k_deg(const int* __restrict__ ei, const int* __restrict__ batch) {
    int i = blockIdx.x * blockDim.x + threadIdx.x;
    if (i < EE) {
        atomicAdd(&d_deg[ei[EE + i]], 1.f);
        atomicAdd(&d_degs[ei[i]], 1);
    }
    if (i < NN) atomicAdd(&d_gcnt[batch[i]], 1.f);
}

// single-block exclusive scan
__global__ void k_scan() {
    __shared__ int s[1024];
    const int t = threadIdx.x;
    const int CHS = (NN + 1023) / 1024;
    int loc[CHS];
    int base = t * CHS;
    int run = 0;
#pragma unroll
    for (int i = 0; i < CHS; i++) {
        int v = (base + i < NN) ? d_degs[base + i] : 0;
        loc[i] = run; run += v;
    }
    s[t] = run;
    __syncthreads();
    for (int off = 1; off < 1024; off <<= 1) {
        int v = (t >= off) ? s[t - off] : 0;
        __syncthreads();
        s[t] += v;
        __syncthreads();
    }
    int excl = (t > 0) ? s[t - 1] : 0;
#pragma unroll
    for (int i = 0; i < CHS; i++)
        if (base + i < NN) {
            int v = excl + loc[i];
            d_start[base + i] = v;
            d_cursor[base + i] = v;
        }
    if (t == 1023) d_start[NN] = s[1023];
}

__global__ void k_scatter(const int* __restrict__ ei) {
    int e = blockIdx.x * blockDim.x + threadIdx.x;
    if (e < EE) {
        int pos = atomicAdd(&d_cursor[ei[e]], 1);
        d_perm[pos] = e;
        d_dsts[pos] = ei[EE + e];
    }
}

// ---------------- both layers' edge-MLP first linear + BN stats --------------
__global__ void k_h_both(const float* __restrict__ ea,
                         const float* __restrict__ w1a, const float* __restrict__ b1a,
                         const float* __restrict__ w1b, const float* __restrict__ b1b) {
    __shared__ float ssum[4 * HID];
    __shared__ float sst[256 * (HP + 1)];
    const int tid  = threadIdx.x;
    const int lane = tid & 31;
    const int p    = blockIdx.x * 256 + tid;          // EE % 256 == 0
    if (tid < 4 * HID) ssum[tid] = 0.f;

    int e = d_perm[p];
    float a0 = ea[3 * e + 0], a1 = ea[3 * e + 1], a2 = ea[3 * e + 2];
    float h0[HID], h1[HID];
#pragma unroll
    for (int k = 0; k < HID; k++) {
        h0[k] = fmaf(a0, __ldg(&w1a[k]),
                fmaf(a1, __ldg(&w1a[HID + k]),
                fmaf(a2, __ldg(&w1a[2 * HID + k]), __ldg(&b1a[k]))));
        h1[k] = fmaf(a0, __ldg(&w1b[k]),
                fmaf(a1, __ldg(&w1b[HID + k]),
                fmaf(a2, __ldg(&w1b[2 * HID + k]), __ldg(&b1b[k]))));
    }
    __syncthreads();

#pragma unroll
    for (int k = 0; k < HID; k++) {
        float s0 = h0[k], q0 = h0[k] * h0[k];
        float s1 = h1[k], q1 = h1[k] * h1[k];
#pragma unroll
        for (int off = 16; off; off >>= 1) {
            s0 += __shfl_down_sync(0xffffffffu, s0, off);
            q0 += __shfl_down_sync(0xffffffffu, q0, off);
            s1 += __shfl_down_sync(0xffffffffu, s1, off);
            q1 += __shfl_down_sync(0xffffffffu, q1, off);
        }
        if (lane == 0) {
            atomicAdd(&ssum[k],           s0);
            atomicAdd(&ssum[HID + k],     q0);
            atomicAdd(&ssum[2 * HID + k], s1);
            atomicAdd(&ssum[3 * HID + k], q1);
        }
    }

    size_t blockBase = (size_t)blockIdx.x * 256 * HP;
    // layer 0 stage + store
#pragma unroll
    for (int k = 0; k < HID; k++) sst[tid * (HP + 1) + k] = h0[k];
#pragma unroll
    for (int k = HID; k < HP; k++) sst[tid * (HP + 1) + k] = 0.f;
    __syncthreads();
    for (int i = tid; i < 256 * HP; i += 256)
        d_h0[blockBase + i] = sst[(i >> 5) * (HP + 1) + (i & 31)];
    __syncthreads();
    // layer 1 stage + store
#pragma unroll
    for (int k = 0; k < HID; k++) sst[tid * (HP + 1) + k] = h1[k];
#pragma unroll
    for (int k = HID; k < HP; k++) sst[tid * (HP + 1) + k] = 0.f;
    __syncthreads();
    for (int i = tid; i < 256 * HP; i += 256)
        d_h1[blockBase + i] = sst[(i >> 5) * (HP + 1) + (i & 31)];

    if (tid < 4 * HID) atomicAdd(&d_sum[tid], (double)ssum[tid]);
}

// ---------------- per-node y[n,k,o] (split-K, w2 row in regs, f32x2) ---------
template <int DIN>
__global__ void k_y(const float* __restrict__ xin_ext, int use_ext,
                    const float* __restrict__ w2, const float* __restrict__ b2) {
    __shared__ float w2s[KB * DIN * DOUT];
    __shared__ float b2s[DIN * DOUT];
    __shared__ __align__(16) float xs[NT * DIN];
    const float* xin = use_ext ? xin_ext : d_x0;
    const int tid = threadIdx.x, wk = tid >> 5, lane = tid & 31;
    const int by = blockIdx.y;
    const bool aux = (wk == KB);

    for (int i = tid; i < KB * DIN * DOUT; i += blockDim.x)
        w2s[i] = w2[by * KB * DIN * DOUT + i];
    if (by == 0)
        for (int i = tid; i < DIN * DOUT; i += blockDim.x) b2s[i] = b2[i];
    __syncthreads();

    float wreg[DIN];
    if (!aux) {
#pragma unroll
        for (int i = 0; i < DIN; i++) wreg[i] = w2s[(wk * DIN + i) * DOUT + lane];
    } else if (by == 0) {
#pragma unroll
        for (int i = 0; i < DIN; i++) wreg[i] = b2s[i * DOUT + lane];
    }
    const int kg = by * KB + wk;
    const int CH = (NN + NB - 1) / NB;
    const int nbeg = blockIdx.x * CH;
    const int nend = min(nbeg + CH, NN);

    for (int n0 = nbeg; n0 < nend; n0 += NT) {
        for (int idx = tid; idx < NT * DIN; idx += blockDim.x) {
            int t = idx / DIN, i = idx % DIN;
            int n = n0 + t;
            xs[i * NT + t] = (n < nend) ? xin[(size_t)n * DIN + i] : 0.f;
        }
        __syncthreads();
        if (!aux) {
            u64 acc0 = 0, acc1 = 0, acc2 = 0, acc3 = 0;
#pragma unroll
            for (int i = 0; i < DIN; i++) {
                u64 ww = pk2(wreg[i], wreg[i]);
                const ulonglong2* xv = (const ulonglong2*)&xs[i * NT];
                ulonglong2 A = xv[0], B = xv[1];
                acc0 = fma2(A.x, ww, acc0);
                acc1 = fma2(A.y, ww, acc1);
                acc2 = fma2(B.x, ww, acc2);
                acc3 = fma2(B.y, ww, acc3);
            }
            float v[NT];
            upk2(acc0, v[0], v[1]); upk2(acc1, v[2], v[3]);
            upk2(acc2, v[4], v[5]); upk2(acc3, v[6], v[7]);
#pragma unroll
            for (int t = 0; t < NT; t++) {
                int n = n0 + t;
                if (n < nend) d_y[((size_t)n * HID + kg) * DOUT + lane] = v[t];
            }
        } else if (by == 0) {
#pragma unroll
            for (int t = 0; t < NT; t++) {
                int n = n0 + t;
                if (n < nend) {
                    float a = 0.f;
#pragma unroll
                    for (int i = 0; i < DIN; i++)
                        a = fmaf(xs[i * NT + t], wreg[i], a);
                    d_xb[n * DOUT + lane]  = a;
                    d_agg[n * DOUT + lane] = 0.f;
                }
            }
        }
        __syncthreads();
    }
}

// ---------------- messages: warp per source node -----------------------------
__global__ void k_msg(int layer, const float* __restrict__ g,
                      const float* __restrict__ be) {
    int gw   = (blockIdx.x * blockDim.x + threadIdx.x) >> 5;
    int lane = threadIdx.x & 31;
    if (gw >= NN) return;
    int beg = d_start[gw], end = d_start[gw + 1];
    if (beg == end) return;

    const float* hbuf = layer ? d_h1 : d_h0;
    float sc = 1.f, sh = 0.f;
    if (lane < HID) {
        int base = layer * 2 * HID;
        double mu  = d_sum[base + lane] * (1.0 / EE);
        double var = d_sum[base + HID + lane] * (1.0 / EE) - mu * mu;
        sc = rsqrtf((float)var + BEPS) * __ldg(&g[lane]);
        sh = __ldg(&be[lane]) - (float)mu * sc;
    }
    float xb = d_xb[gw * DOUT + lane];
    float yreg[HID];
#pragma unroll
    for (int k = 0; k < HID; k++)
        yreg[k] = d_y[((size_t)gw * HID + k) * DOUT + lane];

    for (int p = beg; p < end; p++) {
        float hv = __ldg(&hbuf[(size_t)p * HP + lane]);
        hv = fmaxf(fmaf(hv, sc, sh), 0.f);
        float m0 = xb, m1 = 0.f;
#pragma unroll
        for (int k = 0; k < HID; k += 2) {
            m0 = fmaf(__shfl_sync(0xffffffffu, hv, k), yreg[k], m0);
            if (k + 1 < HID)
                m1 = fmaf(__shfl_sync(0xffffffffu, hv, k + 1), yreg[k + 1], m1);
        }
        atomicAdd(&d_agg[d_dsts[p] * DOUT + lane], m0 + m1);
    }
}

// ---------------- node update (+ pooling on last layer) ----------------------
template <int DIN>
__global__ void k_x(const float* __restrict__ xin_ext, int use_ext,
                    const float* __restrict__ wr, const float* __restrict__ bc,
                    const int* __restrict__ batch, int last) {
    int idx = blockIdx.x * blockDim.x + threadIdx.x;
    if (idx >= NN * DOUT) return;
    int n = idx / DOUT, o = idx % DOUT;
    const float* xin = use_ext ? xin_ext : d_x0;
    float root = __ldg(&bc[o]);
#pragma unroll
    for (int i = 0; i < DIN; i++)
        root = fmaf(xin[(size_t)n * DIN + i], __ldg(&wr[i * DOUT + o]), root);
    float dg = fmaxf(d_deg[n], 1.f);
    float v = d_agg[idx] / dg + root;
    v = (v > 0.f) ? v : expm1f(v);
    if (last) atomicAdd(&d_gsum[batch[n] * DOUT + o], v);
    else      d_x0[idx] = v;
}

// ---------------- final fc ---------------------------------------------------
__global__ void kp_out(const float* __restrict__ wfc, const float* __restrict__ bfc,
                       float* __restrict__ out) {
    int g = threadIdx.x;
    if (g < GG) {
        float c = fmaxf(d_gcnt[g], 1.f);
        float acc = 0.f;
#pragma unroll
        for (int o = 0; o < DOUT; o++)
            acc = fmaf(d_gsum[g * DOUT + o] / c, __ldg(&wfc[o]), acc);
        out[g] = acc + bfc[0];
    }
}

// ---------------- launch -----------------------------------------------------
extern "C" void kernel_launch(void* const* d_in, const int* in_sizes, int n_in,
                              void* d_out, int out_size) {
    (void)in_sizes; (void)n_in; (void)out_size;
    const float* x     = (const float*)d_in[0];
    const float* ea    = (const float*)d_in[1];
    const int*   ei    = (const int*)d_in[2];
    const int*   batch = (const int*)d_in[3];
    const float* w1_0 = (const float*)d_in[4];
    const float* b1_0 = (const float*)d_in[5];
    const float* g_0  = (const float*)d_in[6];
    const float* be_0 = (const float*)d_in[7];
    const float* w2_0 = (const float*)d_in[8];
    const float* b2_0 = (const float*)d_in[9];
    const float* wr_0 = (const float*)d_in[10];
    const float* bc_0 = (const float*)d_in[11];
    const float* w1_1 = (const float*)d_in[12];
    const float* b1_1 = (const float*)d_in[13];
    const float* g_1  = (const float*)d_in[14];
    const float* be_1 = (const float*)d_in[15];
    const float* w2_1 = (const float*)d_in[16];
    const float* b2_1 = (const float*)d_in[17];
    const float* wr_1 = (const float*)d_in[18];
    const float* bc_1 = (const float*)d_in[19];
    const float* wfc  = (const float*)d_in[20];
    const float* bfc  = (const float*)d_in[21];
    float* out = (float*)d_out;

    // prologue
    k_init<<<(NN + 255) / 256, 256>>>();
    k_deg<<<(EE + 255) / 256, 256>>>(ei, batch);
    k_scan<<<1, 1024>>>();
    k_scatter<<<(EE + 255) / 256, 256>>>(ei);
    k_h_both<<<EE / 256, 256>>>(ea, w1_0, b1_0, w1_1, b1_1);

    // layer 0
    k_y<16><<<dim3(NB, HID / KB), (KB + 1) * 32>>>(x, 1, w2_0, b2_0);
    k_msg<<<(NN * 32 + 255) / 256, 256>>>(0, g_0, be_0);
    k_x<16><<<(NN * DOUT + 255) / 256, 256>>>(x, 1, wr_0, bc_0, batch, 0);

    // layer 1
    k_y<32><<<dim3(NB, HID / KB), (KB + 1) * 32>>>(nullptr, 0, w2_1, b2_1);
    k_msg<<<(NN * 32 + 255) / 256, 256>>>(1, g_1, be_1);
    k_x<32><<<(NN * DOUT + 255) / 256, 256>>>(nullptr, 0, wr_1, bc_1, batch, 1);

    // fc
    kp_out<<<1, 128>>>(wfc, bfc, out);
}

// round 4
// speedup vs baseline: 1.4003x; 1.4003x over previous
#include <cuda_runtime.h>
#include <math.h>

#define NN   10000
#define EE   160000
#define GG   128
#define HID  25
#define DOUT 32
#define BEPS 1e-5f
#define NX   74          // node-tile blocks in k_y
#define TILE 136         // ceil(NN/NX), even

typedef unsigned long long u64;

// ---------------- f32x2 helpers (bit-exact packed fp32 FMA) ------------------
__device__ __forceinline__ u64 pk2(float a, float b) {
    u64 r; asm("mov.b64 %0, {%1, %2};" : "=l"(r) : "f"(a), "f"(b)); return r;
}
__device__ __forceinline__ u64 fma2(u64 a, u64 b, u64 c) {
    u64 d; asm("fma.rn.f32x2 %0, %1, %2, %3;" : "=l"(d) : "l"(a), "l"(b), "l"(c)); return d;
}
__device__ __forceinline__ void upk2(u64 u, float& a, float& b) {
    asm("mov.b64 {%0, %1}, %2;" : "=f"(a), "=f"(b) : "l"(u));
}

// ---------------- scratch ----------------------------------------------------
__device__ float  d_h[(size_t)EE * HID];        // h pre-BN, sorted-by-src order, [p][k]
__device__ double d_sum[2 * HID];               // BN sum / sumsq
__device__ float  d_scale[HID];
__device__ float  d_shift[HID];
__device__ float  d_y[(size_t)NN * HID * DOUT]; // y[n][k][o]
__device__ float  d_xb[NN * DOUT];
__device__ float  d_agg[NN * DOUT];
__device__ float  d_x0[NN * DOUT];
__device__ float  d_x1[NN * DOUT];
__device__ float  d_deg[NN];                    // dst in-degree (float, for mean)
__device__ int    d_degs[NN];                   // src out-degree
__device__ int    d_start[NN + 1];              // CSR row starts (by src)
__device__ int    d_cursor[NN];
__device__ int    d_perm[EE];                   // sorted pos -> original edge id
__device__ int    d_dsts[EE];                   // dst per sorted pos
__device__ float  d_gsum[GG * DOUT];
__device__ float  d_gcnt[GG];

// ---------------- setup: zero everything that needs it -----------------------
__global__ void k_init() {
    int i = blockIdx.x * blockDim.x + threadIdx.x;
    if (i < NN)        { d_deg[i] = 0.f; d_degs[i] = 0; }
    if (i < 2 * HID)   d_sum[i] = 0.0;
    if (i < GG * DOUT) d_gsum[i] = 0.f;
    if (i < GG)        d_gcnt[i] = 0.f;
}

__global__ void k_deg(const int* __restrict__ ei) {
    int e = blockIdx.x * blockDim.x + threadIdx.x;
    if (e < EE) {
        atomicAdd(&d_deg[ei[EE + e]], 1.f);
        atomicAdd(&d_degs[ei[e]], 1);
    }
}

// single-block exclusive scan of d_degs -> d_start / d_cursor
__global__ void k_scan() {
    __shared__ int s[1024];
    const int t = threadIdx.x;
    const int CH = (NN + 1023) / 1024;   // 10
    int loc[CH];
    int base = t * CH;
    int run = 0;
#pragma unroll
    for (int i = 0; i < CH; i++) {
        int v = (base + i < NN) ? d_degs[base + i] : 0;
        loc[i] = run;
        run += v;
    }
    s[t] = run;
    __syncthreads();
    for (int off = 1; off < 1024; off <<= 1) {
        int v = (t >= off) ? s[t - off] : 0;
        __syncthreads();
        s[t] += v;
        __syncthreads();
    }
    int excl = (t > 0) ? s[t - 1] : 0;
#pragma unroll
    for (int i = 0; i < CH; i++) {
        if (base + i < NN) {
            int v = excl + loc[i];
            d_start[base + i]  = v;
            d_cursor[base + i] = v;
        }
    }
    if (t == 1023) d_start[NN] = s[1023];
}

__global__ void k_scatter(const int* __restrict__ ei) {
    int e = blockIdx.x * blockDim.x + threadIdx.x;
    if (e < EE) {
        int src = ei[e];
        int pos = atomicAdd(&d_cursor[src], 1);
        d_perm[pos] = e;
        d_dsts[pos] = ei[EE + e];
    }
}

// ---------------- edge MLP first linear (sorted order) + BN statistics -------
// one thread per sorted edge position; smem-staged coalesced h stores.
__global__ void k_h(const float* __restrict__ ea, const float* __restrict__ w1,
                    const float* __restrict__ b1) {
    __shared__ float ssum[2 * HID];
    __shared__ float sst[256 * (HID + 1)];
    const int tid  = threadIdx.x;
    const int lane = tid & 31;
    const int p    = blockIdx.x * 256 + tid;
    if (tid < 2 * HID) ssum[tid] = 0.f;

    float h[HID];
    if (p < EE) {
        int e = d_perm[p];
        float a0 = ea[3 * e + 0], a1 = ea[3 * e + 1], a2 = ea[3 * e + 2];
#pragma unroll
        for (int k = 0; k < HID; k++)
            h[k] = fmaf(a0, __ldg(&w1[k]),
                   fmaf(a1, __ldg(&w1[HID + k]),
                   fmaf(a2, __ldg(&w1[2 * HID + k]), __ldg(&b1[k]))));
    } else {
#pragma unroll
        for (int k = 0; k < HID; k++) h[k] = 0.f;
    }
    __syncthreads();   // ssum zeroed

    // warp reduction per column, lane0 -> smem atomics
#pragma unroll
    for (int k = 0; k < HID; k++) {
        float s = h[k], q = h[k] * h[k];
#pragma unroll
        for (int off = 16; off; off >>= 1) {
            s += __shfl_down_sync(0xffffffffu, s, off);
            q += __shfl_down_sync(0xffffffffu, q, off);
        }
        if (lane == 0) {
            atomicAdd(&ssum[k],       s);
            atomicAdd(&ssum[HID + k], q);
        }
        sst[tid * (HID + 1) + k] = h[k];
    }
    __syncthreads();

    // coalesced stores of the block's 256*25 h values
    size_t blockBase = (size_t)blockIdx.x * 256 * HID;
    for (int i = tid; i < 256 * HID; i += 256) {
        size_t gp = blockBase + i;
        if (gp < (size_t)EE * HID)
            d_h[gp] = sst[(i / HID) * (HID + 1) + (i % HID)];
    }
    if (tid < 2 * HID) atomicAdd(&d_sum[tid], (double)ssum[tid]);
}

// BN fold -> scale/shift, then re-zero stats for next layer
__global__ void k_bn(const float* __restrict__ g, const float* __restrict__ be) {
    int k = threadIdx.x;
    if (k < HID) {
        double mu  = d_sum[k] / (double)EE;
        double var = d_sum[HID + k] / (double)EE - mu * mu;
        float rs = rsqrtf((float)var + BEPS);
        float sc = rs * g[k];
        d_scale[k] = sc;
        d_shift[k] = be[k] - (float)mu * sc;
        d_sum[k] = 0.0;
        d_sum[HID + k] = 0.0;
    }
}

// ---------------- per-node precompute y[n,k,o] + xb, zero agg ----------------
// grid (NX, HID+1), 128 threads. Block owns one k (w2 slice in regs, lane=o)
// and a 136-node x-tile staged once in smem transposed [i][t].
// blockIdx.y == HID computes xb (b2) and zeroes agg instead.
template <int DIN>
__global__ void k_y(const float* __restrict__ xin_ext, int use_ext,
                    const float* __restrict__ w2, const float* __restrict__ b2) {
    __shared__ __align__(16) float xs[DIN][TILE];
    const float* xin = use_ext ? xin_ext : d_x0;
    const int tid = threadIdx.x, lane = tid & 31, w = tid >> 5;
    const int k = blockIdx.y;                   // 0..HID (HID = aux plane)
    const int nbeg = blockIdx.x * TILE;

    for (int idx = tid; idx < TILE * DIN; idx += 128) {
        int t = idx / DIN, i = idx % DIN;
        int n = nbeg + t;
        xs[i][t] = (n < NN) ? xin[(size_t)n * DIN + i] : 0.f;
    }
    __syncthreads();

    float wreg[DIN];
    if (k < HID) {
#pragma unroll
        for (int i = 0; i < DIN; i++)
            wreg[i] = __ldg(&w2[(k * DIN + i) * DOUT + lane]);
        for (int p = w; p < TILE / 2; p += 4) {
            u64 acc = 0;
#pragma unroll
            for (int i = 0; i < DIN; i++) {
                u64 xv = *(const u64*)&xs[i][2 * p];        // (node 2p, 2p+1) packed
                acc = fma2(xv, pk2(wreg[i], wreg[i]), acc);
            }
            float va, vb; upk2(acc, va, vb);
            int n = nbeg + 2 * p;
            if (n < NN)     d_y[((size_t)n * HID + k) * DOUT + lane] = va;
            if (n + 1 < NN) d_y[((size_t)(n + 1) * HID + k) * DOUT + lane] = vb;
        }
    } else {
#pragma unroll
        for (int i = 0; i < DIN; i++)
            wreg[i] = __ldg(&b2[i * DOUT + lane]);
        for (int p = w; p < TILE / 2; p += 4) {
            u64 acc = 0;
#pragma unroll
            for (int i = 0; i < DIN; i++) {
                u64 xv = *(const u64*)&xs[i][2 * p];
                acc = fma2(xv, pk2(wreg[i], wreg[i]), acc);
            }
            float va, vb; upk2(acc, va, vb);
            int n = nbeg + 2 * p;
            if (n < NN)     { d_xb[n * DOUT + lane] = va;
                              d_agg[n * DOUT + lane] = 0.f; }
            if (n + 1 < NN) { d_xb[(n + 1) * DOUT + lane] = vb;
                              d_agg[(n + 1) * DOUT + lane] = 0.f; }
        }
    }
}

// ---------------- messages: warp per SOURCE node, y row loaded once ----------
__global__ void k_msg() {
    int gw   = (blockIdx.x * blockDim.x + threadIdx.x) >> 5;
    int lane = threadIdx.x & 31;
    if (gw >= NN) return;
    int s   = gw;
    int beg = d_start[s], end = d_start[s + 1];
    if (beg == end) return;

    float sc = 1.f, sh = 0.f;
    if (lane < HID) { sc = d_scale[lane]; sh = d_shift[lane]; }
    float xb = d_xb[s * DOUT + lane];
    float yreg[HID];
#pragma unroll
    for (int k = 0; k < HID; k++)
        yreg[k] = d_y[((size_t)s * HID + k) * DOUT + lane];

    for (int p = beg; p < end; p++) {
        float hv = 0.f;
        if (lane < HID) hv = d_h[(size_t)p * HID + lane];
        hv = fmaxf(fmaf(hv, sc, sh), 0.f);                 // BN + relu
        float m = xb;
#pragma unroll
        for (int k = 0; k < HID; k++)
            m = fmaf(__shfl_sync(0xffffffffu, hv, k), yreg[k], m);
        atomicAdd(&d_agg[d_dsts[p] * DOUT + lane], m);
    }
}

// ---------------- node update ------------------------------------------------
template <int DIN>
__global__ void k_x(const float* __restrict__ xin_ext, int use_ext,
                    const float* __restrict__ wr, const float* __restrict__ bc,
                    int outsel) {
    int idx = blockIdx.x * blockDim.x + threadIdx.x;
    if (idx >= NN * DOUT) return;
    int n = idx / DOUT, o = idx % DOUT;
    const float* xin = use_ext ? xin_ext : d_x0;
    float root = __ldg(&bc[o]);
#pragma unroll
    for (int i = 0; i < DIN; i++)
        root = fmaf(xin[(size_t)n * DIN + i], __ldg(&wr[i * DOUT + o]), root);
    float dg = fmaxf(d_deg[n], 1.f);
    float v = d_agg[idx] / dg + root;
    v = (v > 0.f) ? v : expm1f(v);
    (outsel ? d_x1 : d_x0)[idx] = v;
}

// ---------------- pool + fc --------------------------------------------------
__global__ void kp_acc(const int* __restrict__ batch) {
    int gw   = (blockIdx.x * blockDim.x + threadIdx.x) >> 5;
    int lane = threadIdx.x & 31;
    if (gw >= NN) return;
    int b = batch[gw];
    atomicAdd(&d_gsum[b * DOUT + lane], d_x1[gw * DOUT + lane]);
    if (lane == 0) atomicAdd(&d_gcnt[b], 1.f);
}

__global__ void kp_out(const float* __restrict__ wfc, const float* __restrict__ bfc,
                       float* __restrict__ out) {
    int g = threadIdx.x;
    if (g < GG) {
        float c = fmaxf(d_gcnt[g], 1.f);
        float acc = 0.f;
#pragma unroll
        for (int o = 0; o < DOUT; o++)
            acc = fmaf(d_gsum[g * DOUT + o] / c, __ldg(&wfc[o]), acc);
        out[g] = acc + bfc[0];
    }
}

// ---------------- launch -----------------------------------------------------
extern "C" void kernel_launch(void* const* d_in, const int* in_sizes, int n_in,
                              void* d_out, int out_size) {
    (void)in_sizes; (void)n_in; (void)out_size;
    const float* x     = (const float*)d_in[0];
    const float* ea    = (const float*)d_in[1];
    const int*   ei    = (const int*)d_in[2];
    const int*   batch = (const int*)d_in[3];
    const float* w1_0 = (const float*)d_in[4];
    const float* b1_0 = (const float*)d_in[5];
    const float* g_0  = (const float*)d_in[6];
    const float* be_0 = (const float*)d_in[7];
    const float* w2_0 = (const float*)d_in[8];
    const float* b2_0 = (const float*)d_in[9];
    const float* wr_0 = (const float*)d_in[10];
    const float* bc_0 = (const float*)d_in[11];
    const float* w1_1 = (const float*)d_in[12];
    const float* b1_1 = (const float*)d_in[13];
    const float* g_1  = (const float*)d_in[14];
    const float* be_1 = (const float*)d_in[15];
    const float* w2_1 = (const float*)d_in[16];
    const float* b2_1 = (const float*)d_in[17];
    const float* wr_1 = (const float*)d_in[18];
    const float* bc_1 = (const float*)d_in[19];
    const float* wfc  = (const float*)d_in[20];
    const float* bfc  = (const float*)d_in[21];
    float* out = (float*)d_out;

    // ---- graph prologue: degrees + CSR-by-src ----
    k_init<<<(NN + 255) / 256, 256>>>();
    k_deg<<<(EE + 255) / 256, 256>>>(ei);
    k_scan<<<1, 1024>>>();
    k_scatter<<<(EE + 255) / 256, 256>>>(ei);

    // ---- layer 0 (din=16) ----
    k_h<<<(EE + 255) / 256, 256>>>(ea, w1_0, b1_0);
    k_bn<<<1, 32>>>(g_0, be_0);
    k_y<16><<<dim3(NX, HID + 1), 128>>>(x, 1, w2_0, b2_0);
    k_msg<<<(NN * 32 + 255) / 256, 256>>>();
    k_x<16><<<(NN * DOUT + 255) / 256, 256>>>(x, 1, wr_0, bc_0, 0);

    // ---- layer 1 (din=32) ----
    k_h<<<(EE + 255) / 256, 256>>>(ea, w1_1, b1_1);
    k_bn<<<1, 32>>>(g_1, be_1);
    k_y<32><<<dim3(NX, HID + 1), 128>>>(nullptr, 0, w2_1, b2_1);
    k_msg<<<(NN * 32 + 255) / 256, 256>>>();
    k_x<32><<<(NN * DOUT + 255) / 256, 256>>>(nullptr, 0, wr_1, bc_1, 1);

    // ---- pool + fc ----
    kp_acc<<<(NN * 32 + 255) / 256, 256>>>(batch);
    kp_out<<<1, 128>>>(wfc, bfc, out);
}

// round 5
// speedup vs baseline: 1.7659x; 1.2611x over previous
#include <cuda_runtime.h>
#include <math.h>

#define NN   10000
#define EE   160000
#define GG   128
#define HID  25
#define DOUT 32
#define BEPS 1e-5f
#define HP   32          // padded h row (floats)
#define NX   74          // node-tile blocks in k_y
#define TILE 136         // ceil(NN/NX), even

typedef unsigned long long u64;

// ---------------- f32x2 helpers (bit-exact packed fp32 FMA) ------------------
__device__ __forceinline__ u64 pk2(float a, float b) {
    u64 r; asm("mov.b64 %0, {%1, %2};" : "=l"(r) : "f"(a), "f"(b)); return r;
}
__device__ __forceinline__ u64 fma2(u64 a, u64 b, u64 c) {
    u64 d; asm("fma.rn.f32x2 %0, %1, %2, %3;" : "=l"(d) : "l"(a), "l"(b), "l"(c)); return d;
}
__device__ __forceinline__ void upk2(u64 u, float& a, float& b) {
    asm("mov.b64 {%0, %1}, %2;" : "=f"(a), "=f"(b) : "l"(u));
}

// ---------------- scratch ----------------------------------------------------
__device__ float  d_h0[(size_t)EE * HP];        // layer0 h pre-BN, ORIGINAL edge order
__device__ float  d_h1[(size_t)EE * HP];        // layer1
__device__ double d_mom[9];                     // S0,S1,S2,M00,M01,M02,M11,M12,M22
__device__ float  d_scale[2 * HID];
__device__ float  d_shift[2 * HID];
__device__ float  d_y[(size_t)NN * HID * DOUT]; // y[n][k][o]
__device__ float  d_xb[NN * DOUT];
__device__ float  d_agg[NN * DOUT];
__device__ float  d_x0[NN * DOUT];
__device__ float  d_deg[NN];                    // dst in-degree
__device__ int    d_degs[NN];                   // src out-degree
__device__ int    d_start[NN + 1];
__device__ int    d_cursor[NN];
__device__ int    d_perm[EE];                   // sorted pos -> original edge id
__device__ int    d_dsts[EE];
__device__ float  d_gsum[GG * DOUT];
__device__ float  d_gcnt[GG];

// ---------------- prologue (default stream) ----------------------------------
__global__ void k_init() {
    int i = blockIdx.x * blockDim.x + threadIdx.x;
    if (i < NN)        { d_deg[i] = 0.f; d_degs[i] = 0; }
    if (i < GG * DOUT) d_gsum[i] = 0.f;
    if (i < GG)        d_gcnt[i] = 0.f;
}

__global__ void k_deg(const int* __restrict__ ei, const int* __restrict__ batch) {
    int i = blockIdx.x * blockDim.x + threadIdx.x;
    if (i < EE) {
        atomicAdd(&d_deg[ei[EE + i]], 1.f);
        atomicAdd(&d_degs[ei[i]], 1);
    }
    if (i < NN) atomicAdd(&d_gcnt[batch[i]], 1.f);
}

__global__ void k_scan() {
    __shared__ int s[1024];
    const int t = threadIdx.x;
    const int CH = (NN + 1023) / 1024;
    int loc[CH];
    int base = t * CH;
    int run = 0;
#pragma unroll
    for (int i = 0; i < CH; i++) {
        int v = (base + i < NN) ? d_degs[base + i] : 0;
        loc[i] = run; run += v;
    }
    s[t] = run;
    __syncthreads();
    for (int off = 1; off < 1024; off <<= 1) {
        int v = (t >= off) ? s[t - off] : 0;
        __syncthreads();
        s[t] += v;
        __syncthreads();
    }
    int excl = (t > 0) ? s[t - 1] : 0;
#pragma unroll
    for (int i = 0; i < CH; i++)
        if (base + i < NN) {
            int v = excl + loc[i];
            d_start[base + i]  = v;
            d_cursor[base + i] = v;
        }
    if (t == 1023) d_start[NN] = s[1023];
}

__global__ void k_scatter(const int* __restrict__ ei) {
    int e = blockIdx.x * blockDim.x + threadIdx.x;
    if (e < EE) {
        int pos = atomicAdd(&d_cursor[ei[e]], 1);
        d_perm[pos] = e;
        d_dsts[pos] = ei[EE + e];
    }
}

// ---------------- stream s1: h for BOTH layers + edge-attr moments -----------
__global__ void k_zero_mom() {
    if (threadIdx.x < 9) d_mom[threadIdx.x] = 0.0;
}

__global__ void k_h_both(const float* __restrict__ ea,
                         const float* __restrict__ w1a, const float* __restrict__ b1a,
                         const float* __restrict__ w1b, const float* __restrict__ b1b) {
    __shared__ float sst[256 * (HP + 1)];
    __shared__ float smom[9 * 8];
    const int tid  = threadIdx.x;
    const int lane = tid & 31;
    const int w    = tid >> 5;
    const int e    = blockIdx.x * 256 + tid;           // EE % 256 == 0
    const size_t blockBase = (size_t)blockIdx.x * 256 * HP;

    float a0 = ea[3 * e + 0], a1 = ea[3 * e + 1], a2 = ea[3 * e + 2];

    // 9 moments, warp reduce -> per-warp smem partials
    float mom[9] = {a0, a1, a2, a0 * a0, a0 * a1, a0 * a2, a1 * a1, a1 * a2, a2 * a2};
#pragma unroll
    for (int j = 0; j < 9; j++) {
        float v = mom[j];
#pragma unroll
        for (int off = 16; off; off >>= 1) v += __shfl_down_sync(0xffffffffu, v, off);
        if (lane == 0) smom[j * 8 + w] = v;
    }

    // layer 0 h: compute, stage, coalesced store (padded to 32)
    {
        float h[HID];
#pragma unroll
        for (int k = 0; k < HID; k++)
            h[k] = fmaf(a0, __ldg(&w1a[k]),
                   fmaf(a1, __ldg(&w1a[HID + k]),
                   fmaf(a2, __ldg(&w1a[2 * HID + k]), __ldg(&b1a[k]))));
#pragma unroll
        for (int k = 0; k < HID; k++) sst[tid * (HP + 1) + k] = h[k];
        __syncthreads();
        for (int i = tid; i < 256 * HP; i += 256) {
            int c = i & 31;
            d_h0[blockBase + i] = (c < HID) ? sst[(i >> 5) * (HP + 1) + c] : 0.f;
        }
        __syncthreads();
    }
    // layer 1 h
    {
        float h[HID];
#pragma unroll
        for (int k = 0; k < HID; k++)
            h[k] = fmaf(a0, __ldg(&w1b[k]),
                   fmaf(a1, __ldg(&w1b[HID + k]),
                   fmaf(a2, __ldg(&w1b[2 * HID + k]), __ldg(&b1b[k]))));
#pragma unroll
        for (int k = 0; k < HID; k++) sst[tid * (HP + 1) + k] = h[k];
        __syncthreads();
        for (int i = tid; i < 256 * HP; i += 256) {
            int c = i & 31;
            d_h1[blockBase + i] = (c < HID) ? sst[(i >> 5) * (HP + 1) + c] : 0.f;
        }
    }

    // block moment reduce -> 9 double atomics per block
    if (tid < 9) {
        float s = 0.f;
#pragma unroll
        for (int j = 0; j < 8; j++) s += smom[tid * 8 + j];
        atomicAdd(&d_mom[tid], (double)s);
    }
}

// BN fold for both layers from moments (analytic, double precision)
__global__ void k_bn_both(const float* __restrict__ g0, const float* __restrict__ be0,
                          const float* __restrict__ g1, const float* __restrict__ be1,
                          const float* __restrict__ w1a, const float* __restrict__ b1a,
                          const float* __restrict__ w1b, const float* __restrict__ b1b) {
    int t = threadIdx.x;
    int layer = t >> 5, k = t & 31;
    if (layer < 2 && k < HID) {
        const float* w1 = layer ? w1b : w1a;
        const float* b1 = layer ? b1b : b1a;
        const float* g  = layer ? g1  : g0;
        const float* be = layer ? be1 : be0;
        double wa = w1[k], wb = w1[HID + k], wc = w1[2 * HID + k], b = b1[k];
        double S0 = d_mom[0], S1 = d_mom[1], S2 = d_mom[2];
        double M00 = d_mom[3], M01 = d_mom[4], M02 = d_mom[5];
        double M11 = d_mom[6], M12 = d_mom[7], M22 = d_mom[8];
        double lin = S0 * wa + S1 * wb + S2 * wc;
        double mu  = (lin + (double)EE * b) / (double)EE;
        double sq  = wa * wa * M00 + M11 * wb * wb + M22 * wc * wc
                   + 2.0 * (wa * wb * M01 + wa * wc * M02 + wb * wc * M12)
                   + 2.0 * b * lin + (double)EE * b * b;
        double var = sq / (double)EE - mu * mu;
        float rs = rsqrtf((float)var + BEPS);
        float sc = rs * g[k];
        d_scale[layer * HID + k] = sc;
        d_shift[layer * HID + k] = be[k] - (float)mu * sc;
    }
}

// ---------------- per-node y[n,k,o] + xb, zero agg (round-4 design) ----------
template <int DIN>
__global__ void k_y(const float* __restrict__ xin_ext, int use_ext,
                    const float* __restrict__ w2, const float* __restrict__ b2) {
    __shared__ __align__(16) float xs[DIN][TILE];
    const float* xin = use_ext ? xin_ext : d_x0;
    const int tid = threadIdx.x, lane = tid & 31, w = tid >> 5;
    const int k = blockIdx.y;
    const int nbeg = blockIdx.x * TILE;

    for (int idx = tid; idx < TILE * DIN; idx += 128) {
        int t = idx / DIN, i = idx % DIN;
        int n = nbeg + t;
        xs[i][t] = (n < NN) ? xin[(size_t)n * DIN + i] : 0.f;
    }
    __syncthreads();

    float wreg[DIN];
    if (k < HID) {
#pragma unroll
        for (int i = 0; i < DIN; i++)
            wreg[i] = __ldg(&w2[(k * DIN + i) * DOUT + lane]);
        for (int p = w; p < TILE / 2; p += 4) {
            u64 acc = 0;
#pragma unroll
            for (int i = 0; i < DIN; i++) {
                u64 xv = *(const u64*)&xs[i][2 * p];
                acc = fma2(xv, pk2(wreg[i], wreg[i]), acc);
            }
            float va, vb; upk2(acc, va, vb);
            int n = nbeg + 2 * p;
            if (n < NN)     d_y[((size_t)n * HID + k) * DOUT + lane] = va;
            if (n + 1 < NN) d_y[((size_t)(n + 1) * HID + k) * DOUT + lane] = vb;
        }
    } else {
#pragma unroll
        for (int i = 0; i < DIN; i++)
            wreg[i] = __ldg(&b2[i * DOUT + lane]);
        for (int p = w; p < TILE / 2; p += 4) {
            u64 acc = 0;
#pragma unroll
            for (int i = 0; i < DIN; i++) {
                u64 xv = *(const u64*)&xs[i][2 * p];
                acc = fma2(xv, pk2(wreg[i], wreg[i]), acc);
            }
            float va, vb; upk2(acc, va, vb);
            int n = nbeg + 2 * p;
            if (n < NN)     { d_xb[n * DOUT + lane] = va;
                              d_agg[n * DOUT + lane] = 0.f; }
            if (n + 1 < NN) { d_xb[(n + 1) * DOUT + lane] = vb;
                              d_agg[(n + 1) * DOUT + lane] = 0.f; }
        }
    }
}

// ---------------- messages: warp per SOURCE node -----------------------------
__global__ void k_msg(int layer) {
    int gw   = (blockIdx.x * blockDim.x + threadIdx.x) >> 5;
    int lane = threadIdx.x & 31;
    if (gw >= NN) return;
    int beg = d_start[gw], end = d_start[gw + 1];
    if (beg == end) return;

    const float* hbuf = layer ? d_h1 : d_h0;
    float sc = 1.f, sh = 0.f;
    if (lane < HID) {
        sc = d_scale[layer * HID + lane];
        sh = d_shift[layer * HID + lane];
    }
    float xb = d_xb[gw * DOUT + lane];
    float yreg[HID];
#pragma unroll
    for (int k = 0; k < HID; k++)
        yreg[k] = d_y[((size_t)gw * HID + k) * DOUT + lane];

    for (int p = beg; p < end; p++) {
        int e = d_perm[p];
        float hv = __ldg(&hbuf[(size_t)e * HP + lane]);
        hv = fmaxf(fmaf(hv, sc, sh), 0.f);
        float m0 = xb, m1 = 0.f;
#pragma unroll
        for (int k = 0; k < HID; k += 2) {
            m0 = fmaf(__shfl_sync(0xffffffffu, hv, k), yreg[k], m0);
            if (k + 1 < HID)
                m1 = fmaf(__shfl_sync(0xffffffffu, hv, k + 1), yreg[k + 1], m1);
        }
        atomicAdd(&d_agg[d_dsts[p] * DOUT + lane], m0 + m1);
    }
}

// ---------------- node update (+ pooling on last layer) ----------------------
template <int DIN>
__global__ void k_x(const float* __restrict__ xin_ext, int use_ext,
                    const float* __restrict__ wr, const float* __restrict__ bc,
                    const int* __restrict__ batch, int last) {
    int idx = blockIdx.x * blockDim.x + threadIdx.x;
    if (idx >= NN * DOUT) return;
    int n = idx / DOUT, o = idx % DOUT;
    const float* xin = use_ext ? xin_ext : d_x0;
    float root = __ldg(&bc[o]);
#pragma unroll
    for (int i = 0; i < DIN; i++)
        root = fmaf(xin[(size_t)n * DIN + i], __ldg(&wr[i * DOUT + o]), root);
    float dg = fmaxf(d_deg[n], 1.f);
    float v = d_agg[idx] / dg + root;
    v = (v > 0.f) ? v : expm1f(v);
    if (last) atomicAdd(&d_gsum[batch[n] * DOUT + o], v);
    else      d_x0[idx] = v;
}

// ---------------- final fc ---------------------------------------------------
__global__ void kp_out(const float* __restrict__ wfc, const float* __restrict__ bfc,
                       float* __restrict__ out) {
    int g = threadIdx.x;
    if (g < GG) {
        float c = fmaxf(d_gcnt[g], 1.f);
        float acc = 0.f;
#pragma unroll
        for (int o = 0; o < DOUT; o++)
            acc = fmaf(d_gsum[g * DOUT + o] / c, __ldg(&wfc[o]), acc);
        out[g] = acc + bfc[0];
    }
}

// ---------------- launch -----------------------------------------------------
extern "C" void kernel_launch(void* const* d_in, const int* in_sizes, int n_in,
                              void* d_out, int out_size) {
    (void)in_sizes; (void)n_in; (void)out_size;
    const float* x     = (const float*)d_in[0];
    const float* ea    = (const float*)d_in[1];
    const int*   ei    = (const int*)d_in[2];
    const int*   batch = (const int*)d_in[3];
    const float* w1_0 = (const float*)d_in[4];
    const float* b1_0 = (const float*)d_in[5];
    const float* g_0  = (const float*)d_in[6];
    const float* be_0 = (const float*)d_in[7];
    const float* w2_0 = (const float*)d_in[8];
    const float* b2_0 = (const float*)d_in[9];
    const float* wr_0 = (const float*)d_in[10];
    const float* bc_0 = (const float*)d_in[11];
    const float* w1_1 = (const float*)d_in[12];
    const float* b1_1 = (const float*)d_in[13];
    const float* g_1  = (const float*)d_in[14];
    const float* be_1 = (const float*)d_in[15];
    const float* w2_1 = (const float*)d_in[16];
    const float* b2_1 = (const float*)d_in[17];
    const float* wr_1 = (const float*)d_in[18];
    const float* bc_1 = (const float*)d_in[19];
    const float* wfc  = (const float*)d_in[20];
    const float* bfc  = (const float*)d_in[21];
    float* out = (float*)d_out;

    // one-time resource creation (host-side, no device memory)
    static cudaStream_t s1 = nullptr, s2 = nullptr;
    static cudaEvent_t ev0, ev1, ev2;
    if (!s1) {
        cudaStreamCreateWithFlags(&s1, cudaStreamNonBlocking);
        cudaStreamCreateWithFlags(&s2, cudaStreamNonBlocking);
        cudaEventCreateWithFlags(&ev0, cudaEventDisableTiming);
        cudaEventCreateWithFlags(&ev1, cudaEventDisableTiming);
        cudaEventCreateWithFlags(&ev2, cudaEventDisableTiming);
    }

    // fork
    cudaEventRecord(ev0, 0);
    cudaStreamWaitEvent(s1, ev0, 0);
    cudaStreamWaitEvent(s2, ev0, 0);

    // default stream: CSR prologue
    k_init<<<(NN + 255) / 256, 256>>>();
    k_deg<<<(EE + 255) / 256, 256>>>(ei, batch);
    k_scan<<<1, 1024>>>();
    k_scatter<<<(EE + 255) / 256, 256>>>(ei);

    // s1: h for both layers + BN folds
    k_zero_mom<<<1, 32, 0, s1>>>();
    k_h_both<<<EE / 256, 256, 0, s1>>>(ea, w1_0, b1_0, w1_1, b1_1);
    k_bn_both<<<1, 64, 0, s1>>>(g_0, be_0, g_1, be_1, w1_0, b1_0, w1_1, b1_1);
    cudaEventRecord(ev1, s1);

    // s2: layer-0 y precompute (depends only on input x)
    k_y<16><<<dim3(NX, HID + 1), 128, 0, s2>>>(x, 1, w2_0, b2_0);
    cudaEventRecord(ev2, s2);

    // join
    cudaStreamWaitEvent(0, ev1, 0);
    cudaStreamWaitEvent(0, ev2, 0);

    // layer 0 tail
    k_msg<<<(NN * 32 + 255) / 256, 256>>>(0);
    k_x<16><<<(NN * DOUT + 255) / 256, 256>>>(x, 1, wr_0, bc_0, batch, 0);

    // layer 1
    k_y<32><<<dim3(NX, HID + 1), 128>>>(nullptr, 0, w2_1, b2_1);
    k_msg<<<(NN * 32 + 255) / 256, 256>>>(1);
    k_x<32><<<(NN * DOUT + 255) / 256, 256>>>(nullptr, 0, wr_1, bc_1, batch, 1);

    // fc
    kp_out<<<1, 128>>>(wfc, bfc, out);
}

// round 7
// speedup vs baseline: 1.8563x; 1.0512x over previous
#include <cuda_runtime.h>
#include <math.h>

#define NN   10000
#define EE   160000
#define GG   128
#define HID  25
#define DOUT 32
#define BEPS 1e-5f
#define HP   32          // padded h row (floats)
#define NX   74          // node-tile blocks in k_y
#define TILE 136         // ceil(NN/NX), even

typedef unsigned long long u64;

// ---------------- f32x2 helpers (bit-exact packed fp32 FMA) ------------------
__device__ __forceinline__ u64 pk2(float a, float b) {
    u64 r; asm("mov.b64 %0, {%1, %2};" : "=l"(r) : "f"(a), "f"(b)); return r;
}
__device__ __forceinline__ u64 fma2(u64 a, u64 b, u64 c) {
    u64 d; asm("fma.rn.f32x2 %0, %1, %2, %3;" : "=l"(d) : "l"(a), "l"(b), "l"(c)); return d;
}
__device__ __forceinline__ void upk2(u64 u, float& a, float& b) {
    asm("mov.b64 {%0, %1}, %2;" : "=f"(a), "=f"(b) : "l"(u));
}

// ---------------- scratch ----------------------------------------------------
__device__ float  d_h0[(size_t)EE * HP];        // layer0 h pre-BN, ORIGINAL edge order
__device__ float  d_h1[(size_t)EE * HP];        // layer1
__device__ double d_mom[9];                     // S0,S1,S2,M00,M01,M02,M11,M12,M22
__device__ float  d_scale[2 * HID];
__device__ float  d_shift[2 * HID];
__device__ float  d_y[(size_t)NN * HID * DOUT]; // y[n][k][o]
__device__ float  d_xb[NN * DOUT];
__device__ float  d_agg[NN * DOUT];
__device__ float  d_x0[NN * DOUT];
__device__ float  d_deg[NN];                    // dst in-degree
__device__ int    d_degs[NN];                   // src out-degree
__device__ int    d_start[NN + 1];
__device__ int    d_cursor[NN];
__device__ int    d_perm[EE];                   // sorted pos -> original edge id
__device__ int    d_dsts[EE];
__device__ float  d_gsum[GG * DOUT];
__device__ float  d_gcnt[GG];

// ---------------- default stream: CSR prologue -------------------------------
__global__ void k_zero_degs() {
    int i = blockIdx.x * blockDim.x + threadIdx.x;
    if (i < NN) d_degs[i] = 0;
}

// 4 edges per thread, int4 loads (EE % 4 == 0)
__global__ void k_deg_src(const int* __restrict__ ei) {
    int i = (blockIdx.x * blockDim.x + threadIdx.x) * 4;
    if (i < EE) {
        int4 s = *(const int4*)(ei + i);
        atomicAdd(&d_degs[s.x], 1);
        atomicAdd(&d_degs[s.y], 1);
        atomicAdd(&d_degs[s.z], 1);
        atomicAdd(&d_degs[s.w], 1);
    }
}

__global__ void k_scan() {
    __shared__ int s[1024];
    const int t = threadIdx.x;
    const int CH = (NN + 1023) / 1024;
    int loc[CH];
    int base = t * CH;
    int run = 0;
#pragma unroll
    for (int i = 0; i < CH; i++) {
        int v = (base + i < NN) ? d_degs[base + i] : 0;
        loc[i] = run; run += v;
    }
    s[t] = run;
    __syncthreads();
    for (int off = 1; off < 1024; off <<= 1) {
        int v = (t >= off) ? s[t - off] : 0;
        __syncthreads();
        s[t] += v;
        __syncthreads();
    }
    int excl = (t > 0) ? s[t - 1] : 0;
#pragma unroll
    for (int i = 0; i < CH; i++)
        if (base + i < NN) {
            int v = excl + loc[i];
            d_start[base + i]  = v;
            d_cursor[base + i] = v;
        }
    if (t == 1023) d_start[NN] = s[1023];
}

// 4 edges per thread, int4 loads of src & dst halves
__global__ void k_scatter(const int* __restrict__ ei) {
    int i = (blockIdx.x * blockDim.x + threadIdx.x) * 4;
    if (i < EE) {
        int4 s = *(const int4*)(ei + i);
        int4 t = *(const int4*)(ei + EE + i);
        int p0 = atomicAdd(&d_cursor[s.x], 1);
        int p1 = atomicAdd(&d_cursor[s.y], 1);
        int p2 = atomicAdd(&d_cursor[s.z], 1);
        int p3 = atomicAdd(&d_cursor[s.w], 1);
        d_perm[p0] = i;     d_dsts[p0] = t.x;
        d_perm[p1] = i + 1; d_dsts[p1] = t.y;
        d_perm[p2] = i + 2; d_dsts[p2] = t.z;
        d_perm[p3] = i + 3; d_dsts[p3] = t.w;
    }
}

// ---------------- stream s2: dst degree + graph counts + zero pools ----------
__global__ void k_zero_misc() {
    int i = blockIdx.x * blockDim.x + threadIdx.x;
    if (i < NN)        d_deg[i] = 0.f;
    if (i < GG * DOUT) d_gsum[i] = 0.f;
    if (i < GG)        d_gcnt[i] = 0.f;
}

__global__ void k_deg_dst(const int* __restrict__ ei, const int* __restrict__ batch) {
    int tid = blockIdx.x * blockDim.x + threadIdx.x;
    int i = tid * 4;
    if (i < EE) {
        int4 t = *(const int4*)(ei + EE + i);
        atomicAdd(&d_deg[t.x], 1.f);
        atomicAdd(&d_deg[t.y], 1.f);
        atomicAdd(&d_deg[t.z], 1.f);
        atomicAdd(&d_deg[t.w], 1.f);
    }
    if (tid < NN) atomicAdd(&d_gcnt[batch[tid]], 1.f);
}

// ---------------- stream s1: h for BOTH layers + edge-attr moments -----------
__global__ void k_zero_mom() {
    if (threadIdx.x < 9) d_mom[threadIdx.x] = 0.0;
}

__global__ void k_h_both(const float* __restrict__ ea,
                         const float* __restrict__ w1a, const float* __restrict__ b1a,
                         const float* __restrict__ w1b, const float* __restrict__ b1b) {
    __shared__ float sst[256 * (HP + 1)];
    __shared__ float smom[9 * 8];
    const int tid  = threadIdx.x;
    const int lane = tid & 31;
    const int w    = tid >> 5;
    const int e    = blockIdx.x * 256 + tid;           // EE % 256 == 0
    const size_t blockBase = (size_t)blockIdx.x * 256 * HP;

    float a0 = ea[3 * e + 0], a1 = ea[3 * e + 1], a2 = ea[3 * e + 2];

    float mom[9] = {a0, a1, a2, a0 * a0, a0 * a1, a0 * a2, a1 * a1, a1 * a2, a2 * a2};
#pragma unroll
    for (int j = 0; j < 9; j++) {
        float v = mom[j];
#pragma unroll
        for (int off = 16; off; off >>= 1) v += __shfl_down_sync(0xffffffffu, v, off);
        if (lane == 0) smom[j * 8 + w] = v;
    }

    {
        float h[HID];
#pragma unroll
        for (int k = 0; k < HID; k++)
            h[k] = fmaf(a0, __ldg(&w1a[k]),
                   fmaf(a1, __ldg(&w1a[HID + k]),
                   fmaf(a2, __ldg(&w1a[2 * HID + k]), __ldg(&b1a[k]))));
#pragma unroll
        for (int k = 0; k < HID; k++) sst[tid * (HP + 1) + k] = h[k];
        __syncthreads();
        for (int i = tid; i < 256 * HP; i += 256) {
            int c = i & 31;
            d_h0[blockBase + i] = (c < HID) ? sst[(i >> 5) * (HP + 1) + c] : 0.f;
        }
        __syncthreads();
    }
    {
        float h[HID];
#pragma unroll
        for (int k = 0; k < HID; k++)
            h[k] = fmaf(a0, __ldg(&w1b[k]),
                   fmaf(a1, __ldg(&w1b[HID + k]),
                   fmaf(a2, __ldg(&w1b[2 * HID + k]), __ldg(&b1b[k]))));
#pragma unroll
        for (int k = 0; k < HID; k++) sst[tid * (HP + 1) + k] = h[k];
        __syncthreads();
        for (int i = tid; i < 256 * HP; i += 256) {
            int c = i & 31;
            d_h1[blockBase + i] = (c < HID) ? sst[(i >> 5) * (HP + 1) + c] : 0.f;
        }
    }

    if (tid < 9) {
        float s = 0.f;
#pragma unroll
        for (int j = 0; j < 8; j++) s += smom[tid * 8 + j];
        atomicAdd(&d_mom[tid], (double)s);
    }
}

__global__ void k_bn_both(const float* __restrict__ g0, const float* __restrict__ be0,
                          const float* __restrict__ g1, const float* __restrict__ be1,
                          const float* __restrict__ w1a, const float* __restrict__ b1a,
                          const float* __restrict__ w1b, const float* __restrict__ b1b) {
    int t = threadIdx.x;
    int layer = t >> 5, k = t & 31;
    if (layer < 2 && k < HID) {
        const float* w1 = layer ? w1b : w1a;
        const float* b1 = layer ? b1b : b1a;
        const float* g  = layer ? g1  : g0;
        const float* be = layer ? be1 : be0;
        double wa = w1[k], wb = w1[HID + k], wc = w1[2 * HID + k], b = b1[k];
        double S0 = d_mom[0], S1 = d_mom[1], S2 = d_mom[2];
        double M00 = d_mom[3], M01 = d_mom[4], M02 = d_mom[5];
        double M11 = d_mom[6], M12 = d_mom[7], M22 = d_mom[8];
        double lin = S0 * wa + S1 * wb + S2 * wc;
        double mu  = (lin + (double)EE * b) / (double)EE;
        double sq  = wa * wa * M00 + M11 * wb * wb + M22 * wc * wc
                   + 2.0 * (wa * wb * M01 + wa * wc * M02 + wb * wc * M12)
                   + 2.0 * b * lin + (double)EE * b * b;
        double var = sq / (double)EE - mu * mu;
        float rs = rsqrtf((float)var + BEPS);
        float sc = rs * g[k];
        d_scale[layer * HID + k] = sc;
        d_shift[layer * HID + k] = be[k] - (float)mu * sc;
    }
}

// ---------------- per-node y[n,k,o] + xb, zero agg ---------------------------
template <int DIN>
__global__ void k_y(const float* __restrict__ xin_ext, int use_ext,
                    const float* __restrict__ w2, const float* __restrict__ b2) {
    __shared__ __align__(16) float xs[DIN][TILE];
    const float* xin = use_ext ? xin_ext : d_x0;
    const int tid = threadIdx.x, lane = tid & 31, w = tid >> 5;
    const int k = blockIdx.y;
    const int nbeg = blockIdx.x * TILE;

    for (int idx = tid; idx < TILE * DIN; idx += 128) {
        int t = idx / DIN, i = idx % DIN;
        int n = nbeg + t;
        xs[i][t] = (n < NN) ? xin[(size_t)n * DIN + i] : 0.f;
    }
    __syncthreads();

    float wreg[DIN];
    if (k < HID) {
#pragma unroll
        for (int i = 0; i < DIN; i++)
            wreg[i] = __ldg(&w2[(k * DIN + i) * DOUT + lane]);
        for (int p = w; p < TILE / 2; p += 4) {
            u64 acc = 0;
#pragma unroll
            for (int i = 0; i < DIN; i++) {
                u64 xv = *(const u64*)&xs[i][2 * p];
                acc = fma2(xv, pk2(wreg[i], wreg[i]), acc);
            }
            float va, vb; upk2(acc, va, vb);
            int n = nbeg + 2 * p;
            if (n < NN)     d_y[((size_t)n * HID + k) * DOUT + lane] = va;
            if (n + 1 < NN) d_y[((size_t)(n + 1) * HID + k) * DOUT + lane] = vb;
        }
    } else {
#pragma unroll
        for (int i = 0; i < DIN; i++)
            wreg[i] = __ldg(&b2[i * DOUT + lane]);
        for (int p = w; p < TILE / 2; p += 4) {
            u64 acc = 0;
#pragma unroll
            for (int i = 0; i < DIN; i++) {
                u64 xv = *(const u64*)&xs[i][2 * p];
                acc = fma2(xv, pk2(wreg[i], wreg[i]), acc);
            }
            float va, vb; upk2(acc, va, vb);
            int n = nbeg + 2 * p;
            if (n < NN)     { d_xb[n * DOUT + lane] = va;
                              d_agg[n * DOUT + lane] = 0.f; }
            if (n + 1 < NN) { d_xb[(n + 1) * DOUT + lane] = vb;
                              d_agg[(n + 1) * DOUT + lane] = 0.f; }
        }
    }
}

// ---------------- messages: warp per source node, pipelined h loads ----------
__global__ void k_msg(int layer) {
    int gw   = (blockIdx.x * blockDim.x + threadIdx.x) >> 5;
    int lane = threadIdx.x & 31;
    if (gw >= NN) return;
    int beg = d_start[gw], end = d_start[gw + 1];
    if (beg == end) return;

    const float* hbuf = layer ? d_h1 : d_h0;
    float sc = 1.f, sh = 0.f;
    if (lane < HID) {
        sc = d_scale[layer * HID + lane];
        sh = d_shift[layer * HID + lane];
    }
    float xb = d_xb[gw * DOUT + lane];
    float yreg[HID];
#pragma unroll
    for (int k = 0; k < HID; k++)
        yreg[k] = d_y[((size_t)gw * HID + k) * DOUT + lane];

    // software pipeline: prefetch next edge's h row + dst
    int   e0       = d_perm[beg];
    float hv_next  = __ldg(&hbuf[(size_t)e0 * HP + lane]);   // rows padded: lanes 25-31 read 0
    int   dst_next = d_dsts[beg];

    for (int p = beg; p < end; p++) {
        float hv  = hv_next;
        int   dst = dst_next;
        if (p + 1 < end) {
            int e2   = d_perm[p + 1];
            hv_next  = __ldg(&hbuf[(size_t)e2 * HP + lane]);
            dst_next = d_dsts[p + 1];
        }
        hv = fmaxf(fmaf(hv, sc, sh), 0.f);
        float m0 = xb, m1 = 0.f;
#pragma unroll
        for (int k = 0; k < HID; k += 2) {
            m0 = fmaf(__shfl_sync(0xffffffffu, hv, k), yreg[k], m0);
            if (k + 1 < HID)
                m1 = fmaf(__shfl_sync(0xffffffffu, hv, k + 1), yreg[k + 1], m1);
        }
        atomicAdd(&d_agg[dst * DOUT + lane], m0 + m1);
    }
}

// ---------------- node update (+ pooling on last layer) ----------------------
template <int DIN>
__global__ void k_x(const float* __restrict__ xin_ext, int use_ext,
                    const float* __restrict__ wr, const float* __restrict__ bc,
                    const int* __restrict__ batch, int last) {
    int idx = blockIdx.x * blockDim.x + threadIdx.x;
    if (idx >= NN * DOUT) return;
    int n = idx / DOUT, o = idx % DOUT;
    const float* xin = use_ext ? xin_ext : d_x0;
    float root = __ldg(&bc[o]);
#pragma unroll
    for (int i = 0; i < DIN; i++)
        root = fmaf(xin[(size_t)n * DIN + i], __ldg(&wr[i * DOUT + o]), root);
    float dg = fmaxf(d_deg[n], 1.f);
    float v = d_agg[idx] / dg + root;
    v = (v > 0.f) ? v : expm1f(v);
    if (last) atomicAdd(&d_gsum[batch[n] * DOUT + o], v);
    else      d_x0[idx] = v;
}

// ---------------- final fc ---------------------------------------------------
__global__ void kp_out(const float* __restrict__ wfc, const float* __restrict__ bfc,
                       float* __restrict__ out) {
    int g = threadIdx.x;
    if (g < GG) {
        float c = fmaxf(d_gcnt[g], 1.f);
        float acc = 0.f;
#pragma unroll
        for (int o = 0; o < DOUT; o++)
            acc = fmaf(d_gsum[g * DOUT + o] / c, __ldg(&wfc[o]), acc);
        out[g] = acc + bfc[0];
    }
}

// ---------------- launch -----------------------------------------------------
extern "C" void kernel_launch(void* const* d_in, const int* in_sizes, int n_in,
                              void* d_out, int out_size) {
    (void)in_sizes; (void)n_in; (void)out_size;
    const float* x     = (const float*)d_in[0];
    const float* ea    = (const float*)d_in[1];
    const int*   ei    = (const int*)d_in[2];
    const int*   batch = (const int*)d_in[3];
    const float* w1_0 = (const float*)d_in[4];
    const float* b1_0 = (const float*)d_in[5];
    const float* g_0  = (const float*)d_in[6];
    const float* be_0 = (const float*)d_in[7];
    const float* w2_0 = (const float*)d_in[8];
    const float* b2_0 = (const float*)d_in[9];
    const float* wr_0 = (const float*)d_in[10];
    const float* bc_0 = (const float*)d_in[11];
    const float* w1_1 = (const float*)d_in[12];
    const float* b1_1 = (const float*)d_in[13];
    const float* g_1  = (const float*)d_in[14];
    const float* be_1 = (const float*)d_in[15];
    const float* w2_1 = (const float*)d_in[16];
    const float* b2_1 = (const float*)d_in[17];
    const float* wr_1 = (const float*)d_in[18];
    const float* bc_1 = (const float*)d_in[19];
    const float* wfc  = (const float*)d_in[20];
    const float* bfc  = (const float*)d_in[21];
    float* out = (float*)d_out;

    static cudaStream_t s1 = nullptr, s2 = nullptr;
    static cudaEvent_t ev0, ev1, ev2;
    if (!s1) {
        cudaStreamCreateWithFlags(&s1, cudaStreamNonBlocking);
        cudaStreamCreateWithFlags(&s2, cudaStreamNonBlocking);
        cudaEventCreateWithFlags(&ev0, cudaEventDisableTiming);
        cudaEventCreateWithFlags(&ev1, cudaEventDisableTiming);
        cudaEventCreateWithFlags(&ev2, cudaEventDisableTiming);
    }

    // fork
    cudaEventRecord(ev0, 0);
    cudaStreamWaitEvent(s1, ev0, 0);
    cudaStreamWaitEvent(s2, ev0, 0);

    // default: CSR prologue (critical path to k_msg)
    k_zero_degs<<<(NN + 255) / 256, 256>>>();
    k_deg_src<<<(EE / 4 + 255) / 256, 256>>>(ei);
    k_scan<<<1, 1024>>>();
    k_scatter<<<(EE / 4 + 255) / 256, 256>>>(ei);

    // s1: h for both layers + BN folds
    k_zero_mom<<<1, 32, 0, s1>>>();
    k_h_both<<<EE / 256, 256, 0, s1>>>(ea, w1_0, b1_0, w1_1, b1_1);
    k_bn_both<<<1, 64, 0, s1>>>(g_0, be_0, g_1, be_1, w1_0, b1_0, w1_1, b1_1);
    cudaEventRecord(ev1, s1);

    // s2: dst degree + pool counts + layer-0 y precompute
    k_zero_misc<<<(NN + 255) / 256, 256, 0, s2>>>();
    k_deg_dst<<<(EE / 4 + 255) / 256, 256, 0, s2>>>(ei, batch);
    k_y<16><<<dim3(NX, HID + 1), 128, 0, s2>>>(x, 1, w2_0, b2_0);
    cudaEventRecord(ev2, s2);

    // join
    cudaStreamWaitEvent(0, ev1, 0);
    cudaStreamWaitEvent(0, ev2, 0);

    // layer 0 tail
    k_msg<<<(NN * 32 + 255) / 256, 256>>>(0);
    k_x<16><<<(NN * DOUT + 255) / 256, 256>>>(x, 1, wr_0, bc_0, batch, 0);

    // layer 1
    k_y<32><<<dim3(NX, HID + 1), 128>>>(nullptr, 0, w2_1, b2_1);
    k_msg<<<(NN * 32 + 255) / 256, 256>>>(1);
    k_x<32><<<(NN * DOUT + 255) / 256, 256>>>(nullptr, 0, wr_1, bc_1, batch, 1);

    // fc
    kp_out<<<1, 128>>>(wfc, bfc, out);
}

// round 8
// speedup vs baseline: 1.8580x; 1.0009x over previous
#include <cuda_runtime.h>
#include <math.h>

#define NN   10000
#define EE   160000
#define GG   128
#define HID  25
#define DOUT 32
#define BEPS 1e-5f
#define HP   32          // padded h row (floats)
#define NX   74          // node-tile blocks in k_y
#define TILE 136         // ceil(NN/NX), even

typedef unsigned long long u64;

// ---------------- f32x2 helpers (bit-exact packed fp32 FMA) ------------------
__device__ __forceinline__ u64 pk2(float a, float b) {
    u64 r; asm("mov.b64 %0, {%1, %2};" : "=l"(r) : "f"(a), "f"(b)); return r;
}
__device__ __forceinline__ u64 fma2(u64 a, u64 b, u64 c) {
    u64 d; asm("fma.rn.f32x2 %0, %1, %2, %3;" : "=l"(d) : "l"(a), "l"(b), "l"(c)); return d;
}
__device__ __forceinline__ void upk2(u64 u, float& a, float& b) {
    asm("mov.b64 {%0, %1}, %2;" : "=f"(a), "=f"(b) : "l"(u));
}

// ---------------- scratch ----------------------------------------------------
__device__ float  d_h0[(size_t)EE * HP];        // layer0 hn (BN+relu applied), orig order
__device__ float  d_h1[(size_t)EE * HP];        // layer1
__device__ double d_mom[9];                     // S0,S1,S2,M00,M01,M02,M11,M12,M22
__device__ float  d_wf[2][3][32];               // BN-folded first-linear weights
__device__ float  d_bf[2][32];                  // BN-folded bias
__device__ float  d_y[(size_t)NN * HID * DOUT]; // y[n][k][o]
__device__ float  d_xb[NN * DOUT];
__device__ float  d_agg[NN * DOUT];
__device__ float  d_x0[NN * DOUT];
__device__ float  d_deg[NN];                    // dst in-degree
__device__ int    d_degs[NN];                   // src out-degree
__device__ int    d_start[NN + 1];
__device__ int    d_cursor[NN];
__device__ int    d_perm[EE];                   // sorted pos -> original edge id
__device__ int    d_dsts[EE];
__device__ float  d_gsum[GG * DOUT];
__device__ float  d_gcnt[GG];

// ---------------- default stream: CSR prologue -------------------------------
// 4 edges per thread, int4 loads (EE % 4 == 0)
__global__ void k_deg_src(const int* __restrict__ ei) {
    int i = (blockIdx.x * blockDim.x + threadIdx.x) * 4;
    if (i < EE) {
        int4 s = *(const int4*)(ei + i);
        atomicAdd(&d_degs[s.x], 1);
        atomicAdd(&d_degs[s.y], 1);
        atomicAdd(&d_degs[s.z], 1);
        atomicAdd(&d_degs[s.w], 1);
    }
}

__global__ void k_scan() {
    __shared__ int s[1024];
    const int t = threadIdx.x;
    const int CH = (NN + 1023) / 1024;
    int loc[CH];
    int base = t * CH;
    int run = 0;
#pragma unroll
    for (int i = 0; i < CH; i++) {
        int v = (base + i < NN) ? d_degs[base + i] : 0;
        loc[i] = run; run += v;
    }
    s[t] = run;
    __syncthreads();
    for (int off = 1; off < 1024; off <<= 1) {
        int v = (t >= off) ? s[t - off] : 0;
        __syncthreads();
        s[t] += v;
        __syncthreads();
    }
    int excl = (t > 0) ? s[t - 1] : 0;
#pragma unroll
    for (int i = 0; i < CH; i++)
        if (base + i < NN) {
            int v = excl + loc[i];
            d_start[base + i]  = v;
            d_cursor[base + i] = v;
        }
    if (t == 1023) d_start[NN] = s[1023];
}

__global__ void k_scatter(const int* __restrict__ ei) {
    int i = (blockIdx.x * blockDim.x + threadIdx.x) * 4;
    if (i < EE) {
        int4 s = *(const int4*)(ei + i);
        int4 t = *(const int4*)(ei + EE + i);
        int p0 = atomicAdd(&d_cursor[s.x], 1);
        int p1 = atomicAdd(&d_cursor[s.y], 1);
        int p2 = atomicAdd(&d_cursor[s.z], 1);
        int p3 = atomicAdd(&d_cursor[s.w], 1);
        d_perm[p0] = i;     d_dsts[p0] = t.x;
        d_perm[p1] = i + 1; d_dsts[p1] = t.y;
        d_perm[p2] = i + 2; d_dsts[p2] = t.z;
        d_perm[p3] = i + 3; d_dsts[p3] = t.w;
    }
}

// ---------------- stream s2: dst degree + graph counts -----------------------
__global__ void k_deg_dst(const int* __restrict__ ei, const int* __restrict__ batch) {
    int tid = blockIdx.x * blockDim.x + threadIdx.x;
    int i = tid * 4;
    if (i < EE) {
        int4 t = *(const int4*)(ei + EE + i);
        atomicAdd(&d_deg[t.x], 1.f);
        atomicAdd(&d_deg[t.y], 1.f);
        atomicAdd(&d_deg[t.z], 1.f);
        atomicAdd(&d_deg[t.w], 1.f);
    }
    if (tid < NN) atomicAdd(&d_gcnt[batch[tid]], 1.f);
}

// ---------------- stream s1: edge-attr moments (4 edges/thread) --------------
__global__ void k_mom(const float* __restrict__ ea) {
    __shared__ float smom[9 * 8];
    const int tid = threadIdx.x;
    const int t = blockIdx.x * 256 + tid;
    float m[9] = {0.f, 0.f, 0.f, 0.f, 0.f, 0.f, 0.f, 0.f, 0.f};
    int base = t * 12;                               // 48B-aligned
    if (base < EE * 3) {
        const float4* p = (const float4*)(ea + base);
        float4 A = p[0], B = p[1], C = p[2];
        float ax[4] = {A.x, A.w, B.z, C.y};
        float ay[4] = {A.y, B.x, B.w, C.z};
        float az[4] = {A.z, B.y, C.x, C.w};
#pragma unroll
        for (int j = 0; j < 4; j++) {
            float a0 = ax[j], a1 = ay[j], a2 = az[j];
            m[0] += a0; m[1] += a1; m[2] += a2;
            m[3] = fmaf(a0, a0, m[3]); m[4] = fmaf(a0, a1, m[4]);
            m[5] = fmaf(a0, a2, m[5]); m[6] = fmaf(a1, a1, m[6]);
            m[7] = fmaf(a1, a2, m[7]); m[8] = fmaf(a2, a2, m[8]);
        }
    }
    int lane = tid & 31, w = tid >> 5;
#pragma unroll
    for (int j = 0; j < 9; j++) {
        float v = m[j];
#pragma unroll
        for (int off = 16; off; off >>= 1) v += __shfl_down_sync(0xffffffffu, v, off);
        if (lane == 0) smom[j * 8 + w] = v;
    }
    __syncthreads();
    if (tid < 9) {
        float s = 0.f;
#pragma unroll
        for (int j = 0; j < 8; j++) s += smom[tid * 8 + j];
        atomicAdd(&d_mom[tid], (double)s);
    }
}

// BN fold from moments -> folded first-linear weights (both layers)
__global__ void k_bn_both(const float* __restrict__ g0, const float* __restrict__ be0,
                          const float* __restrict__ g1, const float* __restrict__ be1,
                          const float* __restrict__ w1a, const float* __restrict__ b1a,
                          const float* __restrict__ w1b, const float* __restrict__ b1b) {
    int t = threadIdx.x;
    int layer = t >> 5, k = t & 31;
    if (layer < 2 && k < HID) {
        const float* w1 = layer ? w1b : w1a;
        const float* b1 = layer ? b1b : b1a;
        const float* g  = layer ? g1  : g0;
        const float* be = layer ? be1 : be0;
        double wa = w1[k], wb = w1[HID + k], wc = w1[2 * HID + k], b = b1[k];
        double S0 = d_mom[0], S1 = d_mom[1], S2 = d_mom[2];
        double M00 = d_mom[3], M01 = d_mom[4], M02 = d_mom[5];
        double M11 = d_mom[6], M12 = d_mom[7], M22 = d_mom[8];
        double lin = S0 * wa + S1 * wb + S2 * wc;
        double mu  = (lin + (double)EE * b) / (double)EE;
        double sq  = wa * wa * M00 + M11 * wb * wb + M22 * wc * wc
                   + 2.0 * (wa * wb * M01 + wa * wc * M02 + wb * wc * M12)
                   + 2.0 * b * lin + (double)EE * b * b;
        double var = sq / (double)EE - mu * mu;
        float rs = rsqrtf((float)var + BEPS);
        float sc = rs * g[k];
        float sh = be[k] - (float)mu * sc;
        d_wf[layer][0][k] = (float)wa * sc;
        d_wf[layer][1][k] = (float)wb * sc;
        d_wf[layer][2][k] = (float)wc * sc;
        d_bf[layer][k]    = (float)b * sc + sh;
    }
}

// h for both layers with BN+relu pre-applied (folded weights)
__global__ void k_h_both(const float* __restrict__ ea) {
    __shared__ float sst[256 * (HP + 1)];
    const int tid = threadIdx.x;
    const int e = blockIdx.x * 256 + tid;            // EE % 256 == 0
    const size_t blockBase = (size_t)blockIdx.x * 256 * HP;
    float a0 = ea[3 * e + 0], a1 = ea[3 * e + 1], a2 = ea[3 * e + 2];
#pragma unroll
    for (int l = 0; l < 2; l++) {
        float h[HID];
#pragma unroll
        for (int k = 0; k < HID; k++)
            h[k] = fmaxf(
                fmaf(a0, d_wf[l][0][k],
                fmaf(a1, d_wf[l][1][k],
                fmaf(a2, d_wf[l][2][k], d_bf[l][k]))), 0.f);
#pragma unroll
        for (int k = 0; k < HID; k++) sst[tid * (HP + 1) + k] = h[k];
        __syncthreads();
        float* dst = l ? d_h1 : d_h0;
        for (int i = tid; i < 256 * HP; i += 256) {
            int c = i & 31;
            dst[blockBase + i] = (c < HID) ? sst[(i >> 5) * (HP + 1) + c] : 0.f;
        }
        __syncthreads();
    }
}

// ---------------- per-node y[n,k,o] + xb, zero agg ---------------------------
template <int DIN>
__global__ void k_y(const float* __restrict__ xin_ext, int use_ext,
                    const float* __restrict__ w2, const float* __restrict__ b2) {
    __shared__ __align__(16) float xs[DIN][TILE];
    const float* xin = use_ext ? xin_ext : d_x0;
    const int tid = threadIdx.x, lane = tid & 31, w = tid >> 5;
    const int k = blockIdx.y;
    const int nbeg = blockIdx.x * TILE;

    for (int idx = tid; idx < TILE * DIN; idx += 128) {
        int t = idx / DIN, i = idx % DIN;
        int n = nbeg + t;
        xs[i][t] = (n < NN) ? xin[(size_t)n * DIN + i] : 0.f;
    }
    __syncthreads();

    float wreg[DIN];
    if (k < HID) {
#pragma unroll
        for (int i = 0; i < DIN; i++)
            wreg[i] = __ldg(&w2[(k * DIN + i) * DOUT + lane]);
        for (int p = w; p < TILE / 2; p += 4) {
            u64 acc = 0;
#pragma unroll
            for (int i = 0; i < DIN; i++) {
                u64 xv = *(const u64*)&xs[i][2 * p];
                acc = fma2(xv, pk2(wreg[i], wreg[i]), acc);
            }
            float va, vb; upk2(acc, va, vb);
            int n = nbeg + 2 * p;
            if (n < NN)     d_y[((size_t)n * HID + k) * DOUT + lane] = va;
            if (n + 1 < NN) d_y[((size_t)(n + 1) * HID + k) * DOUT + lane] = vb;
        }
    } else {
#pragma unroll
        for (int i = 0; i < DIN; i++)
            wreg[i] = __ldg(&b2[i * DOUT + lane]);
        for (int p = w; p < TILE / 2; p += 4) {
            u64 acc = 0;
#pragma unroll
            for (int i = 0; i < DIN; i++) {
                u64 xv = *(const u64*)&xs[i][2 * p];
                acc = fma2(xv, pk2(wreg[i], wreg[i]), acc);
            }
            float va, vb; upk2(acc, va, vb);
            int n = nbeg + 2 * p;
            if (n < NN)     { d_xb[n * DOUT + lane] = va;
                              d_agg[n * DOUT + lane] = 0.f; }
            if (n + 1 < NN) { d_xb[(n + 1) * DOUT + lane] = vb;
                              d_agg[(n + 1) * DOUT + lane] = 0.f; }
        }
    }
}

// ---------------- messages: warp/src, smem-broadcast h pairs, fma2 -----------
__global__ void k_msg(int layer) {
    __shared__ __align__(16) float sw[8][2][32];
    const int wip  = threadIdx.x >> 5;
    const int gw   = (blockIdx.x * blockDim.x + threadIdx.x) >> 5;
    const int lane = threadIdx.x & 31;
    if (gw >= NN) return;
    int beg = d_start[gw], end = d_start[gw + 1];
    if (beg == end) return;

    const float* hbuf = layer ? d_h1 : d_h0;
    float xb = d_xb[gw * DOUT + lane];
    const float* yrow = d_y + (size_t)gw * HID * DOUT;
    u64 yp[12]; float y24;
#pragma unroll
    for (int k = 0; k < 12; k++)
        yp[k] = pk2(yrow[(2 * k) * DOUT + lane], yrow[(2 * k + 1) * DOUT + lane]);
    y24 = yrow[24 * DOUT + lane];

    int   e0       = d_perm[beg];
    float hv_next  = hbuf[(size_t)e0 * HP + lane];      // normalized+relu'd already
    int   dst_next = d_dsts[beg];

    for (int p = beg; p < end; p++) {
        int buf = p & 1;
        sw[wip][buf][lane] = hv_next;
        int dst = dst_next;
        if (p + 1 < end) {
            int e2   = d_perm[p + 1];
            hv_next  = hbuf[(size_t)e2 * HP + lane];
            dst_next = d_dsts[p + 1];
        }
        __syncwarp();
        const u64* hp = (const u64*)sw[wip][buf];
        u64 acc = 0;
#pragma unroll
        for (int k = 0; k < 12; k++) acc = fma2(hp[k], yp[k], acc);
        float ma, mb; upk2(acc, ma, mb);
        float m = fmaf(sw[wip][buf][24], y24, xb + ma + mb);
        atomicAdd(&d_agg[dst * DOUT + lane], m);
    }
}

// ---------------- node update (+ pooling on last layer) ----------------------
template <int DIN>
__global__ void k_x(const float* __restrict__ xin_ext, int use_ext,
                    const float* __restrict__ wr, const float* __restrict__ bc,
                    const int* __restrict__ batch, int last) {
    int idx = blockIdx.x * blockDim.x + threadIdx.x;
    if (idx >= NN * DOUT) return;
    int n = idx / DOUT, o = idx % DOUT;
    const float* xin = use_ext ? xin_ext : d_x0;
    float root = __ldg(&bc[o]);
#pragma unroll
    for (int i = 0; i < DIN; i++)
        root = fmaf(xin[(size_t)n * DIN + i], __ldg(&wr[i * DOUT + o]), root);
    float dg = fmaxf(d_deg[n], 1.f);
    float v = d_agg[idx] / dg + root;
    v = (v > 0.f) ? v : expm1f(v);
    if (last) atomicAdd(&d_gsum[batch[n] * DOUT + o], v);
    else      d_x0[idx] = v;
}

// ---------------- final fc ---------------------------------------------------
__global__ void kp_out(const float* __restrict__ wfc, const float* __restrict__ bfc,
                       float* __restrict__ out) {
    int g = threadIdx.x;
    if (g < GG) {
        float c = fmaxf(d_gcnt[g], 1.f);
        float acc = 0.f;
#pragma unroll
        for (int o = 0; o < DOUT; o++)
            acc = fmaf(d_gsum[g * DOUT + o] / c, __ldg(&wfc[o]), acc);
        out[g] = acc + bfc[0];
    }
}

// ---------------- launch -----------------------------------------------------
extern "C" void kernel_launch(void* const* d_in, const int* in_sizes, int n_in,
                              void* d_out, int out_size) {
    (void)in_sizes; (void)n_in; (void)out_size;
    const float* x     = (const float*)d_in[0];
    const float* ea    = (const float*)d_in[1];
    const int*   ei    = (const int*)d_in[2];
    const int*   batch = (const int*)d_in[3];
    const float* w1_0 = (const float*)d_in[4];
    const float* b1_0 = (const float*)d_in[5];
    const float* g_0  = (const float*)d_in[6];
    const float* be_0 = (const float*)d_in[7];
    const float* w2_0 = (const float*)d_in[8];
    const float* b2_0 = (const float*)d_in[9];
    const float* wr_0 = (const float*)d_in[10];
    const float* bc_0 = (const float*)d_in[11];
    const float* w1_1 = (const float*)d_in[12];
    const float* b1_1 = (const float*)d_in[13];
    const float* g_1  = (const float*)d_in[14];
    const float* be_1 = (const float*)d_in[15];
    const float* w2_1 = (const float*)d_in[16];
    const float* b2_1 = (const float*)d_in[17];
    const float* wr_1 = (const float*)d_in[18];
    const float* bc_1 = (const float*)d_in[19];
    const float* wfc  = (const float*)d_in[20];
    const float* bfc  = (const float*)d_in[21];
    float* out = (float*)d_out;

    static cudaStream_t s1 = nullptr, s2 = nullptr;
    static cudaEvent_t ev0, ev1, ev2;
    static void *p_degs, *p_deg, *p_gsum, *p_gcnt, *p_mom;
    if (!s1) {
        cudaStreamCreateWithFlags(&s1, cudaStreamNonBlocking);
        cudaStreamCreateWithFlags(&s2, cudaStreamNonBlocking);
        cudaEventCreateWithFlags(&ev0, cudaEventDisableTiming);
        cudaEventCreateWithFlags(&ev1, cudaEventDisableTiming);
        cudaEventCreateWithFlags(&ev2, cudaEventDisableTiming);
        cudaGetSymbolAddress(&p_degs, d_degs);
        cudaGetSymbolAddress(&p_deg,  d_deg);
        cudaGetSymbolAddress(&p_gsum, d_gsum);
        cudaGetSymbolAddress(&p_gcnt, d_gcnt);
        cudaGetSymbolAddress(&p_mom,  d_mom);
    }

    // fork
    cudaEventRecord(ev0, 0);
    cudaStreamWaitEvent(s1, ev0, 0);
    cudaStreamWaitEvent(s2, ev0, 0);

    // default: CSR prologue (critical path to k_msg)
    cudaMemsetAsync(p_degs, 0, NN * sizeof(int), 0);
    k_deg_src<<<(EE / 4 + 255) / 256, 256>>>(ei);
    k_scan<<<1, 1024>>>();
    k_scatter<<<(EE / 4 + 255) / 256, 256>>>(ei);

    // s1: moments -> BN fold -> normalized h for both layers
    cudaMemsetAsync(p_mom, 0, 9 * sizeof(double), s1);
    k_mom<<<(EE / 4 + 255) / 256, 256, 0, s1>>>(ea);
    k_bn_both<<<1, 64, 0, s1>>>(g_0, be_0, g_1, be_1, w1_0, b1_0, w1_1, b1_1);
    k_h_both<<<EE / 256, 256, 0, s1>>>(ea);
    cudaEventRecord(ev1, s1);

    // s2: dst degree + pool counts + layer-0 y precompute
    cudaMemsetAsync(p_deg,  0, NN * sizeof(float), s2);
    cudaMemsetAsync(p_gsum, 0, GG * DOUT * sizeof(float), s2);
    cudaMemsetAsync(p_gcnt, 0, GG * sizeof(float), s2);
    k_deg_dst<<<(EE / 4 + 255) / 256, 256, 0, s2>>>(ei, batch);
    k_y<16><<<dim3(NX, HID + 1), 128, 0, s2>>>(x, 1, w2_0, b2_0);
    cudaEventRecord(ev2, s2);

    // join
    cudaStreamWaitEvent(0, ev1, 0);
    cudaStreamWaitEvent(0, ev2, 0);

    // layer 0 tail
    k_msg<<<(NN * 32 + 255) / 256, 256>>>(0);
    k_x<16><<<(NN * DOUT + 255) / 256, 256>>>(x, 1, wr_0, bc_0, batch, 0);

    // layer 1
    k_y<32><<<dim3(NX, HID + 1), 128>>>(nullptr, 0, w2_1, b2_1);
    k_msg<<<(NN * 32 + 255) / 256, 256>>>(1);
    k_x<32><<<(NN * DOUT + 255) / 256, 256>>>(nullptr, 0, wr_1, bc_1, batch, 1);

    // fc
    kp_out<<<1, 128>>>(wfc, bfc, out);
}